// round 1
// baseline (speedup 1.0000x reference)
#include <cuda_runtime.h>
#include <cstdint>

#define B_  8
#define S_  2048
#define N_  4096
#define D_  256
#define MAX_W_ 16

// One span handled by 64 threads; each thread owns one float4 (4 floats) of D=256.
// blockDim = 256 -> 4 spans per block.
__global__ __launch_bounds__(256) void pooling_span_kernel(
    const float* __restrict__ seq,      // [B, S, D]
    const int*   __restrict__ spans,    // [B, N, 2]
    float*       __restrict__ out)      // [B, N, D]
{
    const int span = blockIdx.x * 4 + (threadIdx.x >> 6);   // 0 .. B*N-1
    const int lane = threadIdx.x & 63;                      // float4 index within D

    // span -> (b, n)
    const int b = span >> 12;   // N_ = 4096 = 2^12

    const int start = spans[2 * span];
    const int end   = spans[2 * span + 1];
    const int width = end - start;

    const float4* __restrict__ base =
        reinterpret_cast<const float4*>(seq) + (size_t)b * (S_ * (D_ / 4));

    float4 acc = make_float4(0.f, 0.f, 0.f, 0.f);
    int cnt = 0;

#pragma unroll
    for (int w = 0; w < MAX_W_; ++w) {
        const int raw = end - w;
        if ((w <= width) && (raw >= 0)) {
            const int idx = raw < 0 ? 0 : raw;   // max(raw, 0) — raw>=0 here, kept for exactness
            const float4 v = __ldg(&base[idx * (D_ / 4) + lane]);
            acc.x += v.x; acc.y += v.y; acc.z += v.z; acc.w += v.w;
            ++cnt;
        }
    }

    const float inv = 1.0f / fmaxf((float)cnt, 1e-13f);
    float4 r;
    r.x = acc.x * inv; r.y = acc.y * inv; r.z = acc.z * inv; r.w = acc.w * inv;

    reinterpret_cast<float4*>(out)[(size_t)span * (D_ / 4) + lane] = r;
}

extern "C" void kernel_launch(void* const* d_in, const int* in_sizes, int n_in,
                              void* d_out, int out_size)
{
    const float* seq   = (const float*)d_in[0];   // sequence_tensor [B,S,D] f32
    const int*   spans = (const int*)  d_in[1];   // span_indices    [B,N,2] i32
    float*       out   = (float*)d_out;           // [B,N,D] f32

    const int total_spans = B_ * N_;              // 32768
    const int blocks = total_spans / 4;           // 8192 blocks of 256 threads
    pooling_span_kernel<<<blocks, 256>>>(seq, spans, out);
}